// round 4
// baseline (speedup 1.0000x reference)
#include <cuda_runtime.h>

// Problem constants (fixed-shape problem)
#define MAXN 100000
#define MAXE 1600000
#define DIN  128
#define DH   128
#define DOUT 16

// Scratch (device globals — no runtime allocation). 16B-aligned for float4/red.v4.
__device__ __align__(16) float g_deg [MAXN];
__device__ __align__(16) float g_dinv[MAXN];
__device__ __align__(16) float g_h   [MAXN * DH];   // h' = dinv * (x@W1)
__device__ __align__(16) float g_agg [MAXN * DH];   // layer-1 aggregation
__device__ __align__(16) float g_g   [MAXN * DOUT]; // g' = dinv * (h2@W2)
__device__ int g_is64;                              // edge_index dtype flag

// ---------------------------------------------------------------------------
// Edge-index dtype probe: if the buffer is int64 (values < 2^32), every odd
// int32 word is the zero hi-word. If it's int32, odd words are real indices.
// ---------------------------------------------------------------------------
__global__ void k_detect(const int* __restrict__ ei) {
    if (blockIdx.x == 0 && threadIdx.x == 0) {
        int is64 = 1;
        for (int i = 1; i < 64; i += 2)
            if (ei[i] != 0) is64 = 0;
        g_is64 = is64;
    }
}

__device__ __forceinline__ int load_idx(const void* __restrict__ ei, int i) {
    if (g_is64) return (int)((const long long*)ei)[i];
    return ((const int*)ei)[i];
}

// ---------------------------------------------------------------------------
// Degree / normalization
// ---------------------------------------------------------------------------
__global__ void k_deg_init(int n) {
    int i = blockIdx.x * blockDim.x + threadIdx.x;
    if (i < n) g_deg[i] = 1.0f;  // self-loop
}

__global__ void k_deg_count(const void* __restrict__ ei, int e) {
    int i = blockIdx.x * blockDim.x + threadIdx.x;
    if (i < e) {
        int d = load_idx(ei, e + i);  // dst row
        atomicAdd(&g_deg[d], 1.0f);
    }
}

__global__ void k_dinv(int n) {
    int i = blockIdx.x * blockDim.x + threadIdx.x;
    if (i < n) g_dinv[i] = rsqrtf(g_deg[i]);  // deg >= 1 always
}

// ---------------------------------------------------------------------------
// GEMM1: h' = dinv * (x @ W1); agg1 init = h' (self-loop term)
// Tile: 64 rows x 128 cols, K-chunks of 32. Block = 256 threads,
// each thread computes 4 rows x 8 cols.
// ---------------------------------------------------------------------------
__global__ void k_gemm1(const float* __restrict__ x,
                        const float* __restrict__ W1, int n) {
    __shared__ float Xs[64][33];    // +1 pad
    __shared__ float Ws[32][128];

    int tid  = threadIdx.x;
    int row0 = blockIdx.x * 64;
    int cx   = tid & 15;   // col group: 16 groups x 8 cols
    int ry   = tid >> 4;   // row group: 16 groups x 4 rows

    float acc[4][8];
#pragma unroll
    for (int i = 0; i < 4; i++)
#pragma unroll
        for (int j = 0; j < 8; j++) acc[i][j] = 0.0f;

    for (int k0 = 0; k0 < DIN; k0 += 32) {
        for (int i = tid; i < 64 * 32; i += 256) {
            int r = i >> 5, c = i & 31;
            int gr = row0 + r;
            Xs[r][c] = (gr < n) ? x[gr * DIN + k0 + c] : 0.0f;
        }
        for (int i = tid; i < 32 * 128; i += 256) {
            int r = i >> 7, c = i & 127;
            Ws[r][c] = W1[(k0 + r) * DH + c];
        }
        __syncthreads();

#pragma unroll
        for (int k = 0; k < 32; k++) {
            float a[4];
#pragma unroll
            for (int i = 0; i < 4; i++) a[i] = Xs[ry * 4 + i][k];
            const float4* bp = (const float4*)&Ws[k][cx * 8];
            float4 b0 = bp[0], b1v = bp[1];
            float b[8] = {b0.x, b0.y, b0.z, b0.w, b1v.x, b1v.y, b1v.z, b1v.w};
#pragma unroll
            for (int i = 0; i < 4; i++)
#pragma unroll
                for (int j = 0; j < 8; j++) acc[i][j] += a[i] * b[j];
        }
        __syncthreads();
    }

#pragma unroll
    for (int i = 0; i < 4; i++) {
        int r = row0 + ry * 4 + i;
        if (r < n) {
            float dv = g_dinv[r];
            float4 v0, v1;
            v0.x = dv * acc[i][0]; v0.y = dv * acc[i][1];
            v0.z = dv * acc[i][2]; v0.w = dv * acc[i][3];
            v1.x = dv * acc[i][4]; v1.y = dv * acc[i][5];
            v1.z = dv * acc[i][6]; v1.w = dv * acc[i][7];
            int idx = r * DH + cx * 8;
            *(float4*)&g_h[idx]       = v0;
            *(float4*)&g_h[idx + 4]   = v1;
            *(float4*)&g_agg[idx]     = v0;
            *(float4*)&g_agg[idx + 4] = v1;
        }
    }
}

// ---------------------------------------------------------------------------
// Scatter layer 1: one warp per edge; lane l handles 4 floats.
// agg1[dst] += h'[src]  (vectorized reduction, red.global.add.v4.f32)
// ---------------------------------------------------------------------------
__global__ void k_scatter1(const void* __restrict__ ei, int e) {
    int w = (blockIdx.x * blockDim.x + threadIdx.x) >> 5;
    int lane = threadIdx.x & 31;
    if (w >= e) return;
    int s = load_idx(ei, w);
    int d = load_idx(ei, e + w);
    float4 v = *(const float4*)&g_h[s * DH + lane * 4];
    float* p = &g_agg[d * DH + lane * 4];
    asm volatile("red.global.add.v4.f32 [%0], {%1,%2,%3,%4};"
                 :: "l"(p), "f"(v.x), "f"(v.y), "f"(v.z), "f"(v.w)
                 : "memory");
}

// ---------------------------------------------------------------------------
// GEMM2 fused: h2 = relu(dinv*agg1 + b1); g = h2 @ W2; g' = dinv*g
// Writes g' to g_g (scatter source) and to d_out (self-loop init).
// ---------------------------------------------------------------------------
__global__ void k_gemm2(const float* __restrict__ W2,
                        const float* __restrict__ b1,
                        float* __restrict__ out, int n) {
    __shared__ float Hs[64][129];       // padded
    __shared__ float Ws[128][16];

    int tid  = threadIdx.x;
    int row0 = blockIdx.x * 64;

    for (int i = tid; i < DH * DOUT; i += 256) Ws[i >> 4][i & 15] = W2[i];

    for (int i = tid; i < 64 * DH; i += 256) {
        int r = i >> 7, c = i & 127;
        int gr = row0 + r;
        float v = 0.0f;
        if (gr < n) {
            v = g_dinv[gr] * g_agg[gr * DH + c] + b1[c];
            v = fmaxf(v, 0.0f);
        }
        Hs[r][c] = v;
    }
    __syncthreads();

    for (int t = tid; t < 64 * DOUT; t += 256) {
        int r = t >> 4, j = t & 15;
        int gr = row0 + r;
        if (gr >= n) continue;
        float s = 0.0f;
#pragma unroll
        for (int k = 0; k < DH; k++) s += Hs[r][k] * Ws[k][j];
        float gv = g_dinv[gr] * s;
        g_g[gr * DOUT + j] = gv;
        out[gr * DOUT + j] = gv;   // self-loop init (also un-poisons d_out)
    }
}

// ---------------------------------------------------------------------------
// Scatter layer 2: 4 threads per edge, each handles 4 of 16 floats.
// out[dst] += g'[src]
// ---------------------------------------------------------------------------
__global__ void k_scatter2(const void* __restrict__ ei,
                           float* __restrict__ out, int e) {
    int t = blockIdx.x * blockDim.x + threadIdx.x;
    int ee = t >> 2, c = t & 3;
    if (ee >= e) return;
    int s = load_idx(ei, ee);
    int d = load_idx(ei, e + ee);
    float4 v = *(const float4*)&g_g[s * DOUT + c * 4];
    float* p = &out[d * DOUT + c * 4];
    asm volatile("red.global.add.v4.f32 [%0], {%1,%2,%3,%4};"
                 :: "l"(p), "f"(v.x), "f"(v.y), "f"(v.z), "f"(v.w)
                 : "memory");
}

// ---------------------------------------------------------------------------
// Final: out = dinv[row]*out + b2[col]   (in place)
// ---------------------------------------------------------------------------
__global__ void k_final(const float* __restrict__ b2,
                        float* __restrict__ out, int n16) {
    int i = blockIdx.x * blockDim.x + threadIdx.x;
    if (i < n16) {
        int r = i >> 4;
        out[i] = g_dinv[r] * out[i] + b2[i & 15];
    }
}

// ---------------------------------------------------------------------------
extern "C" void kernel_launch(void* const* d_in, const int* in_sizes, int n_in,
                              void* d_out, int out_size) {
    const float* x  = (const float*)d_in[0];
    const void*  ei = d_in[1];                 // int32 or int64, probed on device
    const float* W1 = (const float*)d_in[2];
    const float* b1 = (const float*)d_in[3];
    const float* W2 = (const float*)d_in[4];
    const float* b2 = (const float*)d_in[5];
    float*       out = (float*)d_out;

    int n = in_sizes[0] / DIN;   // 100000
    int e = in_sizes[1] / 2;     // 1600000 (element count identical for i32/i64)

    k_detect<<<1, 32>>>((const int*)ei);

    k_deg_init<<<(n + 255) / 256, 256>>>(n);
    k_deg_count<<<(e + 255) / 256, 256>>>(ei, e);
    k_dinv<<<(n + 255) / 256, 256>>>(n);

    k_gemm1<<<(n + 63) / 64, 256>>>(x, W1, n);

    {
        long long threads = (long long)e * 32;
        int blocks = (int)((threads + 255) / 256);
        k_scatter1<<<blocks, 256>>>(ei, e);
    }

    k_gemm2<<<(n + 63) / 64, 256>>>(W2, b1, out, n);

    {
        long long threads = (long long)e * 4;
        int blocks = (int)((threads + 255) / 256);
        k_scatter2<<<blocks, 256>>>(ei, out, e);
    }

    k_final<<<(n * DOUT + 255) / 256, 256>>>(b2, out, n * DOUT);
}

// round 6
// speedup vs baseline: 1.4141x; 1.4141x over previous
#include <cuda_runtime.h>

// Problem constants (fixed-shape problem)
#define MAXN 100000
#define MAXE 1600000
#define DIN  128
#define DH   128
#define DOUT 16

// Scratch (device globals — no runtime allocation). 16B-aligned for float4.
__device__ __align__(16) float g_dinv[MAXN];
__device__ __align__(16) float g_h   [MAXN * DH];   // h' = dinv * (x@W1)
__device__ __align__(16) float g_agg [MAXN * DH];   // layer-1 aggregation
__device__ __align__(16) float g_g   [MAXN * DOUT]; // g' = dinv * (h2@W2)
__device__ int g_cnt [MAXN];      // in-degree (excl. self-loop)
__device__ int g_rs  [MAXN];      // CSR row start (exclusive scan of cnt)
__device__ int g_cur [MAXN];      // fill cursor
__device__ int g_bsum[256];       // scan partials
__device__ int g_boff[256];
__device__ int g_csr [MAXE];      // src index per edge, grouped by dst
__device__ int g_is64;            // edge_index dtype flag

// ---------------------------------------------------------------------------
// Edge-index dtype probe: int64 with values < 2^32 -> all odd int32 words zero.
// ---------------------------------------------------------------------------
__global__ void k_detect(const int* __restrict__ ei) {
    if (blockIdx.x == 0 && threadIdx.x == 0) {
        int is64 = 1;
        for (int i = 1; i < 64; i += 2)
            if (ei[i] != 0) is64 = 0;
        g_is64 = is64;
    }
}

__device__ __forceinline__ int load_idx(const void* __restrict__ ei, int i) {
    if (g_is64) return (int)((const long long*)ei)[i];
    return ((const int*)ei)[i];
}

// ---------------------------------------------------------------------------
// CSR build: zero -> histogram(dst) -> scan -> fill
// ---------------------------------------------------------------------------
__global__ void k_zero(int n) {
    int i = blockIdx.x * blockDim.x + threadIdx.x;
    if (i < n) g_cnt[i] = 0;
}

__global__ void k_hist(const void* __restrict__ ei, int e) {
    int i = blockIdx.x * blockDim.x + threadIdx.x;
    if (i < e) atomicAdd(&g_cnt[load_idx(ei, e + i)], 1);
}

// Block-level inclusive scan (1024/block) -> exclusive per-element + block sums
__global__ void k_scan_block(int n) {
    __shared__ int s[1024];
    int t = threadIdx.x;
    int i = blockIdx.x * 1024 + t;
    int v = (i < n) ? g_cnt[i] : 0;
    s[t] = v;
    __syncthreads();
#pragma unroll
    for (int off = 1; off < 1024; off <<= 1) {
        int u = (t >= off) ? s[t - off] : 0;
        __syncthreads();
        s[t] += u;
        __syncthreads();
    }
    if (i < n) g_rs[i] = s[t] - v;
    if (t == 1023) g_bsum[blockIdx.x] = s[1023];
}

__global__ void k_scan_tot(int nb) {
    __shared__ int s[128];
    int t = threadIdx.x;
    int v = (t < nb) ? g_bsum[t] : 0;
    s[t] = v;
    __syncthreads();
#pragma unroll
    for (int off = 1; off < 128; off <<= 1) {
        int u = (t >= off) ? s[t - off] : 0;
        __syncthreads();
        s[t] += u;
        __syncthreads();
    }
    if (t < nb) g_boff[t] = s[t] - v;
}

// finalize row starts, zero cursors, compute dinv = rsqrt(deg+1)
__global__ void k_scan_add(int n) {
    int i = blockIdx.x * blockDim.x + threadIdx.x;
    if (i < n) {
        g_rs[i] += g_boff[i >> 10];
        g_cur[i] = 0;
        g_dinv[i] = rsqrtf((float)(g_cnt[i] + 1));
    }
}

__global__ void k_fill(const void* __restrict__ ei, int e) {
    int i = blockIdx.x * blockDim.x + threadIdx.x;
    if (i < e) {
        int s = load_idx(ei, i);
        int d = load_idx(ei, e + i);
        int pos = g_rs[d] + atomicAdd(&g_cur[d], 1);
        g_csr[pos] = s;
    }
}

// ---------------------------------------------------------------------------
// GEMM1: h' = dinv * (x @ W1)
// Tile: 64 rows x 128 cols, K-chunks of 32. Block 256, thread = 4 rows x 8 cols.
// ---------------------------------------------------------------------------
__global__ void k_gemm1(const float* __restrict__ x,
                        const float* __restrict__ W1, int n) {
    __shared__ float Xs[64][33];
    __shared__ float Ws[32][128];

    int tid  = threadIdx.x;
    int row0 = blockIdx.x * 64;
    int cx   = tid & 15;
    int ry   = tid >> 4;

    float acc[4][8];
#pragma unroll
    for (int i = 0; i < 4; i++)
#pragma unroll
        for (int j = 0; j < 8; j++) acc[i][j] = 0.0f;

    for (int k0 = 0; k0 < DIN; k0 += 32) {
        for (int i = tid; i < 64 * 32; i += 256) {
            int r = i >> 5, c = i & 31;
            int gr = row0 + r;
            Xs[r][c] = (gr < n) ? x[gr * DIN + k0 + c] : 0.0f;
        }
        for (int i = tid; i < 32 * 128; i += 256) {
            int r = i >> 7, c = i & 127;
            Ws[r][c] = W1[(k0 + r) * DH + c];
        }
        __syncthreads();

#pragma unroll
        for (int k = 0; k < 32; k++) {
            float a[4];
#pragma unroll
            for (int i = 0; i < 4; i++) a[i] = Xs[ry * 4 + i][k];
            const float4* bp = (const float4*)&Ws[k][cx * 8];
            float4 b0 = bp[0], b1v = bp[1];
            float b[8] = {b0.x, b0.y, b0.z, b0.w, b1v.x, b1v.y, b1v.z, b1v.w};
#pragma unroll
            for (int i = 0; i < 4; i++)
#pragma unroll
                for (int j = 0; j < 8; j++) acc[i][j] += a[i] * b[j];
        }
        __syncthreads();
    }

#pragma unroll
    for (int i = 0; i < 4; i++) {
        int r = row0 + ry * 4 + i;
        if (r < n) {
            float dv = g_dinv[r];
            float4 v0, v1;
            v0.x = dv * acc[i][0]; v0.y = dv * acc[i][1];
            v0.z = dv * acc[i][2]; v0.w = dv * acc[i][3];
            v1.x = dv * acc[i][4]; v1.y = dv * acc[i][5];
            v1.z = dv * acc[i][6]; v1.w = dv * acc[i][7];
            int idx = r * DH + cx * 8;
            *(float4*)&g_h[idx]     = v0;
            *(float4*)&g_h[idx + 4] = v1;
        }
    }
}

// ---------------------------------------------------------------------------
// Gather layer 1 (atomic-free): warp per node.
// agg[v] = h'[v] + sum_{src in-edges} h'[src]; lane owns one float4 column slice.
// ---------------------------------------------------------------------------
__global__ void k_gather1(int n) {
    int w = (blockIdx.x * blockDim.x + threadIdx.x) >> 5;
    int lane = threadIdx.x & 31;
    if (w >= n) return;
    int row = g_rs[w];
    int deg = g_cnt[w];
    int col = lane * 4;

    float4 acc = *(const float4*)&g_h[w * DH + col];  // self-loop
    for (int j = 0; j < deg; j++) {
        int s = g_csr[row + j];                        // broadcast load
        float4 v = *(const float4*)&g_h[s * DH + col];
        acc.x += v.x; acc.y += v.y; acc.z += v.z; acc.w += v.w;
    }
    *(float4*)&g_agg[w * DH + col] = acc;
}

// ---------------------------------------------------------------------------
// GEMM2 fused: h2 = relu(dinv*agg + b1); g' = dinv * (h2 @ W2) -> g_g
// Thread owns (row, float4 of 4 output cols): 1 scalar LDS + 1 LDS.128 per 4 FMA.
// ---------------------------------------------------------------------------
__global__ void k_gemm2(const float* __restrict__ W2,
                        const float* __restrict__ b1, int n) {
    __shared__ float Hs[64][129];
    __shared__ float Ws[128][16];

    int tid  = threadIdx.x;
    int row0 = blockIdx.x * 64;

    for (int i = tid; i < DH * DOUT; i += 256) Ws[i >> 4][i & 15] = W2[i];

    for (int i = tid; i < 64 * DH; i += 256) {
        int r = i >> 7, c = i & 127;
        int gr = row0 + r;
        float v = 0.0f;
        if (gr < n) {
            v = g_dinv[gr] * g_agg[gr * DH + c] + b1[c];
            v = fmaxf(v, 0.0f);
        }
        Hs[r][c] = v;
    }
    __syncthreads();

    int r  = tid >> 2;        // 0..63
    int j4 = tid & 3;         // float4 group of output cols
    int gr = row0 + r;
    if (gr >= n) return;

    float4 acc = make_float4(0.f, 0.f, 0.f, 0.f);
#pragma unroll
    for (int k = 0; k < DH; k++) {
        float a = Hs[r][k];
        float4 wv = *(const float4*)&Ws[k][j4 * 4];
        acc.x += a * wv.x; acc.y += a * wv.y;
        acc.z += a * wv.z; acc.w += a * wv.w;
    }
    float dv = g_dinv[gr];
    acc.x *= dv; acc.y *= dv; acc.z *= dv; acc.w *= dv;
    *(float4*)&g_g[gr * DOUT + j4 * 4] = acc;
}

// ---------------------------------------------------------------------------
// Gather layer 2 + epilogue: warp per node, 8 edges/iter x 4 lanes x float4.
// out[v] = dinv[v]*(g'[v] + sum g'[src]) + b2
// ---------------------------------------------------------------------------
__global__ void k_gather2(const float* __restrict__ b2,
                          float* __restrict__ out, int n) {
    int w = (blockIdx.x * blockDim.x + threadIdx.x) >> 5;
    int lane = threadIdx.x & 31;
    if (w >= n) return;
    int row = g_rs[w];
    int deg = g_cnt[w];
    int g = lane >> 2;    // edge sub-slot 0..7
    int c = lane & 3;     // float4 component group

    float4 acc = make_float4(0.f, 0.f, 0.f, 0.f);
    for (int base = 0; base < deg; base += 8) {
        int j = base + g;
        if (j < deg) {
            int s = g_csr[row + j];
            float4 v = *(const float4*)&g_g[s * DOUT + c * 4];
            acc.x += v.x; acc.y += v.y; acc.z += v.z; acc.w += v.w;
        }
    }
    // reduce across the 8 edge sub-slots (stride 4, 8, 16)
#pragma unroll
    for (int off = 4; off < 32; off <<= 1) {
        acc.x += __shfl_xor_sync(0xFFFFFFFF, acc.x, off);
        acc.y += __shfl_xor_sync(0xFFFFFFFF, acc.y, off);
        acc.z += __shfl_xor_sync(0xFFFFFFFF, acc.z, off);
        acc.w += __shfl_xor_sync(0xFFFFFFFF, acc.w, off);
    }
    if (lane < 4) {
        float4 self = *(const float4*)&g_g[w * DOUT + c * 4];
        float4 bb   = *(const float4*)&b2[c * 4];
        float dv = g_dinv[w];
        float4 o;
        o.x = dv * (acc.x + self.x) + bb.x;
        o.y = dv * (acc.y + self.y) + bb.y;
        o.z = dv * (acc.z + self.z) + bb.z;
        o.w = dv * (acc.w + self.w) + bb.w;
        *(float4*)&out[w * DOUT + c * 4] = o;
    }
}

// ---------------------------------------------------------------------------
extern "C" void kernel_launch(void* const* d_in, const int* in_sizes, int n_in,
                              void* d_out, int out_size) {
    const float* x  = (const float*)d_in[0];
    const void*  ei = d_in[1];                 // int32 or int64, probed on device
    const float* W1 = (const float*)d_in[2];
    const float* b1 = (const float*)d_in[3];
    const float* W2 = (const float*)d_in[4];
    const float* b2 = (const float*)d_in[5];
    float*       out = (float*)d_out;

    int n = in_sizes[0] / DIN;   // 100000
    int e = in_sizes[1] / 2;     // 1600000 (element count identical for i32/i64)
    int nb = (n + 1023) >> 10;   // scan blocks (98)

    k_detect<<<1, 32>>>((const int*)ei);

    // CSR build (also yields degrees -> dinv)
    k_zero<<<(n + 255) / 256, 256>>>(n);
    k_hist<<<(e + 255) / 256, 256>>>(ei, e);
    k_scan_block<<<nb, 1024>>>(n);
    k_scan_tot<<<1, 128>>>(nb);
    k_scan_add<<<(n + 255) / 256, 256>>>(n);
    k_fill<<<(e + 255) / 256, 256>>>(ei, e);

    // Layer 1
    k_gemm1<<<(n + 63) / 64, 256>>>(x, W1, n);
    k_gather1<<<(n * 32 + 255) / 256, 256>>>(n);

    // Layer 2
    k_gemm2<<<(n + 63) / 64, 256>>>(W2, b1, n);
    k_gather2<<<(n * 32 + 255) / 256, 256>>>(b2, out, n);
}